// round 5
// baseline (speedup 1.0000x reference)
#include <cuda_runtime.h>
#include <math.h>
#include <stdint.h>

#define CIN 48
#define CB  8
#define H   4096
#define HV  (H/4)            // 1024 double2 (4 floats) per channel row
#define NTHREADS 1024
#define NWARPS   (NTHREADS/32)
#define NPAIR    36          // upper-triangle incl. diag of 8x8
#define SCALE    0.35355339059327373f   // 1/sqrt(8)

typedef unsigned long long ull;

// ---- dynamic smem layout (bytes) ----
#define OFF_KQ0    0                         // 8*1024 ulonglong2 = 128 KB
#define OFF_GPART  (OFF_KQ0 + 131072)        // 2*32*36 floats = 9216 B
#define OFF_G      (OFF_GPART + 9216)        // 2*64 floats = 512 B
#define OFF_AM     (OFF_G + 512)             // 2*64 floats = 512 B
#define OFF_W2     (OFF_AM + 512)            // 2*384 ull = 6144 B
#define OFF_WD     (OFF_W2 + 6144)           // 384 ull = 3072 B
#define SMEM_TOTAL (OFF_WD + 3072)           // 150528 B

// packed fp32x2 FMA / MUL (SASS FFMA2 — PTX-only on sm_103a)
__device__ __forceinline__ ull fma2(ull a, ull b, ull c) {
    ull d;
    asm("fma.rn.f32x2 %0, %1, %2, %3;" : "=l"(d) : "l"(a), "l"(b), "l"(c));
    return d;
}
__device__ __forceinline__ ull mul2(ull a, ull b) {
    ull d;
    asm("mul.rn.f32x2 %0, %1, %2;" : "=l"(d) : "l"(a), "l"(b));
    return d;
}
__device__ __forceinline__ void unpack2(ull v, float& lo, float& hi) {
    asm("mov.b64 {%0, %1}, %2;" : "=f"(lo), "=f"(hi) : "l"(v));
}
__device__ __forceinline__ ull dup_f32(float f) {
    uint32_t u = __float_as_uint(f);
    return ((ull)u << 32) | (ull)u;
}

__global__ __launch_bounds__(NTHREADS, 1)
void ultimus_kernel(const float* __restrict__ x,
                    const float* __restrict__ wd,   // [8,48]
                    const float* __restrict__ wu,   // [48,8]
                    float* __restrict__ out)
{
    extern __shared__ char smem[];
    ulonglong2* kq0     = (ulonglong2*)(smem + OFF_KQ0);   // [o][t]
    float*      s_gpart = (float*)(smem + OFF_GPART);      // [bb][warp][pair]
    float*      s_G     = (float*)(smem + OFF_G);          // [bb][8][8]
    float*      s_AM    = (float*)(smem + OFF_AM);
    ull*        s_W2d   = (ull*)(smem + OFF_W2);           // [bb][48][8] dup
    ull*        s_wdd   = (ull*)(smem + OFF_WD);           // [8][48] dup

    const int t    = threadIdx.x;
    const int lane = t & 31;
    const int warp = t >> 5;
    const int b0   = blockIdx.x * 2;

    if (t < CB * CIN) s_wdd[t] = dup_f32(wd[t]);
    __syncthreads();

    ull acc2[CB][2];

    // ============ Pass 1 for both batches (b0 stashed to smem) ============
    #pragma unroll
    for (int bb = 0; bb < 2; bb++) {
        const double2* __restrict__ x2 =
            (const double2*)(x + (size_t)(b0 + bb) * CIN * H);

        #pragma unroll
        for (int o = 0; o < CB; o++) { acc2[o][0] = 0ull; acc2[o][1] = 0ull; }

        #pragma unroll 4
        for (int c = 0; c < CIN; c++) {
            double2 xv = __ldcs(&x2[c * HV + t]);
            ull xlo = __double_as_longlong(xv.x);
            ull xhi = __double_as_longlong(xv.y);
            #pragma unroll
            for (int o = 0; o < CB; o++) {
                ull w = s_wdd[o * CIN + c];
                acc2[o][0] = fma2(w, xlo, acc2[o][0]);
                acc2[o][1] = fma2(w, xhi, acc2[o][1]);
            }
        }

        // gram partials for this batch
        {
            float* gp = s_gpart + bb * (NWARPS * NPAIR);
            int base = 0;
            #pragma unroll
            for (int i = 0; i < CB; i++) {
                #pragma unroll
                for (int j = i; j < CB; j++) {
                    ull p = mul2(acc2[i][0], acc2[j][0]);
                    p = fma2(acc2[i][1], acc2[j][1], p);
                    float plo, phi;
                    unpack2(p, plo, phi);
                    float s = plo + phi;
                    #pragma unroll
                    for (int off = 16; off > 0; off >>= 1)
                        s += __shfl_xor_sync(0xffffffffu, s, off);
                    if (lane == 0) gp[warp * NPAIR + base] = s;
                    base++;
                }
            }
        }

        // stash b0's kqv into smem (thread-private slots, no sync needed)
        if (bb == 0) {
            #pragma unroll
            for (int o = 0; o < CB; o++)
                kq0[o * NTHREADS + t] = make_ulonglong2(acc2[o][0], acc2[o][1]);
        }
    }
    __syncthreads();

    // ============ Middle (both batches at once) ============
    if (t < 2 * NPAIR) {
        const int bb = (t >= NPAIR);
        const int pr = bb ? t - NPAIR : t;
        const float* gp = s_gpart + bb * (NWARPS * NPAIR);
        float s = 0.f;
        #pragma unroll
        for (int w = 0; w < NWARPS; w++) s += gp[w * NPAIR + pr];
        int i = 0, rem = pr;
        while (rem >= CB - i) { rem -= CB - i; i++; }
        int j = i + rem;
        s_G[bb * 64 + i * CB + j] = s;
        s_G[bb * 64 + j * CB + i] = s;
    }
    __syncthreads();

    if (t < 2 * CB) {
        const int bb = t >> 3;
        const int row = t & 7;
        const float* G = s_G + bb * 64;
        float v[CB];
        float m = -1e30f;
        #pragma unroll
        for (int j = 0; j < CB; j++) {
            v[j] = G[row * CB + j] * SCALE;
            m = fmaxf(m, v[j]);
        }
        float sum = 0.f;
        #pragma unroll
        for (int j = 0; j < CB; j++) {
            v[j] = __expf(v[j] - m);
            sum += v[j];
        }
        float inv = 1.f / sum;
        #pragma unroll
        for (int j = 0; j < CB; j++) s_AM[bb * 64 + row * CB + j] = v[j] * inv;
    }
    __syncthreads();

    if (t < 2 * CIN * CB) {
        const int bb  = (t >= CIN * CB);
        const int idx = bb ? t - CIN * CB : t;
        const int c = idx >> 3, j = idx & 7;
        const float* AM = s_AM + bb * 64;
        float s = 0.f;
        #pragma unroll
        for (int o = 0; o < CB; o++) s += wu[c * CB + o] * AM[o * CB + j];
        s_W2d[bb * (CIN * CB) + idx] = dup_f32(s);
    }
    __syncthreads();

    // ============ Pass 2: batch1 from regs, then batch0 from stash ============
    #pragma unroll
    for (int bb = 1; bb >= 0; bb--) {
        if (bb == 0) {
            #pragma unroll
            for (int o = 0; o < CB; o++) {
                ulonglong2 v = kq0[o * NTHREADS + t];
                acc2[o][0] = v.x;
                acc2[o][1] = v.y;
            }
        }
        const ull* W2 = s_W2d + bb * (CIN * CB);
        double2* __restrict__ out2 =
            (double2*)(out + (size_t)(b0 + bb) * CIN * H);

        #pragma unroll 4
        for (int c = 0; c < CIN; c++) {
            ull w0 = W2[c * CB + 0];
            ull r0 = mul2(w0, acc2[0][0]);
            ull r1 = mul2(w0, acc2[0][1]);
            #pragma unroll
            for (int o = 1; o < CB; o++) {
                ull w = W2[c * CB + o];
                r0 = fma2(w, acc2[o][0], r0);
                r1 = fma2(w, acc2[o][1], r1);
            }
            double2 rv;
            rv.x = __longlong_as_double((long long)r0);
            rv.y = __longlong_as_double((long long)r1);
            __stwt(&out2[c * HV + t], rv);
        }
    }
}

extern "C" void kernel_launch(void* const* d_in, const int* in_sizes, int n_in,
                              void* d_out, int out_size)
{
    const float* x  = (const float*)d_in[0];   // [256, 48, 4096, 1]
    const float* wd = (const float*)d_in[1];   // [8, 48]
    const float* wu = (const float*)d_in[2];   // [48, 8]
    float* out = (float*)d_out;                // [256, 48, 4096, 1]

    cudaFuncSetAttribute(ultimus_kernel,
                         cudaFuncAttributeMaxDynamicSharedMemorySize, SMEM_TOTAL);
    ultimus_kernel<<<128, NTHREADS, SMEM_TOTAL>>>(x, wd, wu, out);
}

// round 6
// speedup vs baseline: 1.1462x; 1.1462x over previous
#include <cuda_runtime.h>
#include <math.h>
#include <stdint.h>

#define CIN 48
#define CB  8
#define H   4096
#define HV  (H/4)            // 1024 16B-elements per channel row
#define NTHREADS 1024
#define NWARPS   (NTHREADS/32)
#define NPAIR    36
#define SCALE    0.35355339059327373f   // 1/sqrt(8)

#define NCH_CHUNK  4                     // channels per pipeline chunk
#define NCHUNKS    (CIN / NCH_CHUNK)     // 12
#define NSTAGE     3
#define CHUNK_BYTES (NCH_CHUNK * H * 4)  // 65536

typedef unsigned long long ull;

// ---- dynamic smem layout (bytes) ----
#define OFF_RING   0
#define OFF_FULL   (NSTAGE * CHUNK_BYTES)            // 196608
#define OFF_EMPTY  (OFF_FULL + 8 * NSTAGE)
#define OFF_GPART  (OFF_EMPTY + 8 * NSTAGE)          // 196656
#define OFF_G      (OFF_GPART + NWARPS * NPAIR * 4)  // +4608
#define OFF_AM     (OFF_G + 256)
#define OFF_W2     (OFF_AM + 256)
#define OFF_WD     (OFF_W2 + CIN * CB * 8)
#define SMEM_TOTAL (OFF_WD + CIN * CB * 8)           // ~207.9 KB

// ---- packed fp32x2 math (SASS FFMA2 — PTX-only) ----
__device__ __forceinline__ ull fma2(ull a, ull b, ull c) {
    ull d;
    asm("fma.rn.f32x2 %0, %1, %2, %3;" : "=l"(d) : "l"(a), "l"(b), "l"(c));
    return d;
}
__device__ __forceinline__ ull mul2(ull a, ull b) {
    ull d;
    asm("mul.rn.f32x2 %0, %1, %2;" : "=l"(d) : "l"(a), "l"(b));
    return d;
}
__device__ __forceinline__ void unpack2(ull v, float& lo, float& hi) {
    asm("mov.b64 {%0, %1}, %2;" : "=f"(lo), "=f"(hi) : "l"(v));
}
__device__ __forceinline__ ull dup_f32(float f) {
    uint32_t u = __float_as_uint(f);
    return ((ull)u << 32) | (ull)u;
}

// ---- smem/mbarrier helpers ----
__device__ __forceinline__ uint32_t smem_u32(const void* p) {
    uint32_t a;
    asm("{ .reg .u64 t; cvta.to.shared.u64 t, %1; cvt.u32.u64 %0, t; }"
        : "=r"(a) : "l"(p));
    return a;
}
__device__ __forceinline__ void mbar_init(uint32_t a, uint32_t cnt) {
    asm volatile("mbarrier.init.shared.b64 [%0], %1;" :: "r"(a), "r"(cnt) : "memory");
}
__device__ __forceinline__ void mbar_expect_tx(uint32_t a, uint32_t bytes) {
    asm volatile("mbarrier.arrive.expect_tx.shared.b64 _, [%0], %1;"
                 :: "r"(a), "r"(bytes) : "memory");
}
__device__ __forceinline__ void mbar_arrive(uint32_t a) {
    asm volatile("mbarrier.arrive.shared.b64 _, [%0];" :: "r"(a) : "memory");
}
__device__ __forceinline__ void mbar_wait(uint32_t a, uint32_t parity) {
    asm volatile(
        "{\n\t"
        ".reg .pred P;\n"
        "WAIT_%=:\n\t"
        "mbarrier.try_wait.parity.acquire.cta.shared::cta.b64 P, [%0], %1, 0x989680;\n\t"
        "@P bra.uni DONE_%=;\n\t"
        "bra.uni WAIT_%=;\n"
        "DONE_%=:\n\t"
        "}"
        :: "r"(a), "r"(parity) : "memory");
}
__device__ __forceinline__ void bulk_g2s(uint32_t dst, const void* src,
                                         uint32_t bytes, uint32_t mbar) {
    asm volatile(
        "cp.async.bulk.shared::cluster.global.mbarrier::complete_tx::bytes "
        "[%0], [%1], %2, [%3];"
        :: "r"(dst), "l"(src), "r"(bytes), "r"(mbar) : "memory");
}

__global__ __launch_bounds__(NTHREADS, 1)
void ultimus_kernel(const float* __restrict__ x,
                    const float* __restrict__ wd,   // [8,48]
                    const float* __restrict__ wu,   // [48,8]
                    float* __restrict__ out)
{
    extern __shared__ char smem[];
    float* s_gpart = (float*)(smem + OFF_GPART);   // [warp][pair]
    float* s_G     = (float*)(smem + OFF_G);
    float* s_AM    = (float*)(smem + OFF_AM);
    ull*   s_W2d   = (ull*)(smem + OFF_W2);        // [c][o] dup pairs
    ull*   s_wdd   = (ull*)(smem + OFF_WD);        // [c][o] dup pairs (transposed!)

    const uint32_t sb = smem_u32(smem);
    const int b    = blockIdx.x;
    const int t    = threadIdx.x;
    const int lane = t & 31;
    const int warp = t >> 5;

    // transposed duplicated down-weights: s_wdd[c*CB + o] = {wd[o][c], wd[o][c]}
    if (t < CB * CIN) {
        int o = t / CIN, c = t % CIN;
        s_wdd[c * CB + o] = dup_f32(wd[t]);
    }
    if (t == 0) {
        #pragma unroll
        for (int s = 0; s < NSTAGE; s++) {
            mbar_init(sb + OFF_FULL  + 8 * s, 1);
            mbar_init(sb + OFF_EMPTY + 8 * s, NWARPS);
        }
    }
    __syncthreads();

    const char* xb = (const char*)(x + (size_t)b * CIN * H);

    // prime the pipeline: stages 0..2
    if (t == 0) {
        #pragma unroll
        for (int j = 0; j < NSTAGE; j++) {
            mbar_expect_tx(sb + OFF_FULL + 8 * j, CHUNK_BYTES);
            bulk_g2s(sb + OFF_RING + j * CHUNK_BYTES, xb + (size_t)j * CHUNK_BYTES,
                     CHUNK_BYTES, sb + OFF_FULL + 8 * j);
        }
    }

    // ============ Pass 1: kqv = w_down @ x via smem ring ============
    ull acc2[CB][2];
    #pragma unroll
    for (int o = 0; o < CB; o++) { acc2[o][0] = 0ull; acc2[o][1] = 0ull; }

    for (int k = 0; k < NCHUNKS; k++) {
        const int slot = k % NSTAGE;
        const int par  = (k / NSTAGE) & 1;

        mbar_wait(sb + OFF_FULL + 8 * slot, (uint32_t)par);

        const double2* ring = (const double2*)(smem + OFF_RING + slot * CHUNK_BYTES);
        #pragma unroll
        for (int cc = 0; cc < NCH_CHUNK; cc++) {
            const int c = k * NCH_CHUNK + cc;
            double2 xv = ring[cc * HV + t];
            ull xlo = __double_as_longlong(xv.x);
            ull xhi = __double_as_longlong(xv.y);
            const ulonglong2* wp = (const ulonglong2*)(s_wdd + c * CB);
            #pragma unroll
            for (int oo = 0; oo < CB / 2; oo++) {
                ulonglong2 w2v = wp[oo];       // LDS.128: weights for o=2oo, 2oo+1
                acc2[2*oo  ][0] = fma2(w2v.x, xlo, acc2[2*oo  ][0]);
                acc2[2*oo  ][1] = fma2(w2v.x, xhi, acc2[2*oo  ][1]);
                acc2[2*oo+1][0] = fma2(w2v.y, xlo, acc2[2*oo+1][0]);
                acc2[2*oo+1][1] = fma2(w2v.y, xhi, acc2[2*oo+1][1]);
            }
        }

        __syncwarp();
        if (lane == 0) mbar_arrive(sb + OFF_EMPTY + 8 * slot);

        if (t == 0 && k + NSTAGE < NCHUNKS) {
            mbar_wait(sb + OFF_EMPTY + 8 * slot, (uint32_t)par);
            mbar_expect_tx(sb + OFF_FULL + 8 * slot, CHUNK_BYTES);
            bulk_g2s(sb + OFF_RING + slot * CHUNK_BYTES,
                     xb + (size_t)(k + NSTAGE) * CHUNK_BYTES,
                     CHUNK_BYTES, sb + OFF_FULL + 8 * slot);
        }
    }

    // ============ Gram partials ============
    {
        int base = 0;
        #pragma unroll
        for (int i = 0; i < CB; i++) {
            #pragma unroll
            for (int j = i; j < CB; j++) {
                ull p = mul2(acc2[i][0], acc2[j][0]);
                p = fma2(acc2[i][1], acc2[j][1], p);
                float plo, phi;
                unpack2(p, plo, phi);
                float s = plo + phi;
                #pragma unroll
                for (int off = 16; off > 0; off >>= 1)
                    s += __shfl_xor_sync(0xffffffffu, s, off);
                if (lane == 0) s_gpart[warp * NPAIR + base] = s;
                base++;
            }
        }
    }
    __syncthreads();

    if (t < NPAIR) {
        float s = 0.f;
        #pragma unroll
        for (int w = 0; w < NWARPS; w++) s += s_gpart[w * NPAIR + t];
        int i = 0, rem = t;
        while (rem >= CB - i) { rem -= CB - i; i++; }
        int j = i + rem;
        s_G[i * CB + j] = s;
        s_G[j * CB + i] = s;
    }
    __syncthreads();

    // ============ Softmax -> AM ============
    if (t < CB) {
        float v[CB];
        float m = -1e30f;
        #pragma unroll
        for (int j = 0; j < CB; j++) {
            v[j] = s_G[t * CB + j] * SCALE;
            m = fmaxf(m, v[j]);
        }
        float sum = 0.f;
        #pragma unroll
        for (int j = 0; j < CB; j++) {
            v[j] = __expf(v[j] - m);
            sum += v[j];
        }
        float inv = 1.f / sum;
        #pragma unroll
        for (int j = 0; j < CB; j++) s_AM[t * CB + j] = v[j] * inv;
    }
    __syncthreads();

    // ============ W2 = w_up @ AM (duplicated pairs) ============
    if (t < CIN * CB) {
        int c = t >> 3, j = t & 7;
        float s = 0.f;
        #pragma unroll
        for (int o = 0; o < CB; o++) s += wu[c * CB + o] * s_AM[o * CB + j];
        s_W2d[c * CB + j] = dup_f32(s);
    }
    __syncthreads();

    // ============ Pass 2: out[c][h] = sum_j W2[c][j] * kqv[j][h] ============
    double2* __restrict__ out2 = (double2*)(out + (size_t)b * CIN * H);

    #pragma unroll 4
    for (int c = 0; c < CIN; c++) {
        const ulonglong2* wp = (const ulonglong2*)(s_W2d + c * CB);
        ulonglong2 wv = wp[0];
        ull r0 = mul2(wv.x, acc2[0][0]);
        ull r1 = mul2(wv.x, acc2[0][1]);
        r0 = fma2(wv.y, acc2[1][0], r0);
        r1 = fma2(wv.y, acc2[1][1], r1);
        #pragma unroll
        for (int oo = 1; oo < CB / 2; oo++) {
            wv = wp[oo];
            r0 = fma2(wv.x, acc2[2*oo  ][0], r0);
            r1 = fma2(wv.x, acc2[2*oo  ][1], r1);
            r0 = fma2(wv.y, acc2[2*oo+1][0], r0);
            r1 = fma2(wv.y, acc2[2*oo+1][1], r1);
        }
        double2 rv;
        rv.x = __longlong_as_double((long long)r0);
        rv.y = __longlong_as_double((long long)r1);
        __stwt(&out2[c * HV + t], rv);
    }
}

extern "C" void kernel_launch(void* const* d_in, const int* in_sizes, int n_in,
                              void* d_out, int out_size)
{
    const float* x  = (const float*)d_in[0];   // [256, 48, 4096, 1]
    const float* wd = (const float*)d_in[1];   // [8, 48]
    const float* wu = (const float*)d_in[2];   // [48, 8]
    float* out = (float*)d_out;                // [256, 48, 4096, 1]

    cudaFuncSetAttribute(ultimus_kernel,
                         cudaFuncAttributeMaxDynamicSharedMemorySize, SMEM_TOTAL);
    ultimus_kernel<<<256, NTHREADS, SMEM_TOTAL>>>(x, wd, wu, out);
}